// round 7
// baseline (speedup 1.0000x reference)
#include <cuda_runtime.h>

// 2-layer bidirectional GRU encoder, B=256, T=256, D=64, H=256.
// Batch-parallel recurrence: each CTA owns Rv batch rows for one direction and
// iterates all T steps locally (no grid sync). Thread (j, half) owns hidden
// index j for RT rows; computes gates (j, H+j, 2H+j) so the GRU update is
// fully in-thread. Inner products use packed fma.rn.f32x2 (2x fp32).
// R6: Rv=4/RT=2 -> 128 CTAs (was 64) to fill the 148-SM chip in one wave.

namespace {
constexpr int Bv  = 256;
constexpr int Tv  = 256;
constexpr int Dv  = 64;
constexpr int Hv  = 256;
constexpr int Rv  = 4;    // batch rows per CTA
constexpr int RT  = 2;    // batch rows per thread
constexpr int NTH = 512;  // threads per CTA (= 2 * Hv)
}

typedef unsigned long long ull;

// Layer-0 output sequence: [T][B][2H] fp32 = 128 MB scratch.
__device__ __align__(16) float g_h1[(size_t)Tv * Bv * 2 * Hv];

__device__ __forceinline__ void ffma2(ull &acc, ull a, ull b) {
    // packed 2-wide fp32 FMA (FFMA2) — PTX-only form
    asm("fma.rn.f32x2 %0, %1, %2, %0;" : "+l"(acc) : "l"(a), "l"(b));
}
__device__ __forceinline__ float hsum2(ull v) {
    return __uint_as_float((unsigned)(v & 0xffffffffull)) +
           __uint_as_float((unsigned)(v >> 32));
}
__device__ __forceinline__ float sigm(float x) {
    return 1.0f / (1.0f + __expf(-x));
}
__device__ __forceinline__ float tanh_fast(float x) {
    float ax = fabsf(x);
    float e  = __expf(-2.0f * ax);
    float t  = (1.0f - e) / (1.0f + e);
    return copysignf(t, x);
}

template<int KIN, bool IS_L0>
__global__ void __launch_bounds__(NTH, 1)
gru_layer(const float* __restrict__ in,     // L0: x (B,T,D). L1: g_h1 (T,B,2H)
          const float* __restrict__ wih,    // (2, 3H, KIN)
          const float* __restrict__ whh,    // (2, 3H, H)
          const float* __restrict__ bih,    // (2, 3H)
          const float* __restrict__ bhh,    // (2, 3H)
          float* __restrict__ seq_out,      // L0: g_h1. L1: unused
          float* __restrict__ fin_out)      // L1: d_out (B, 2H). L0: unused
{
    const int tid = threadIdx.x;
    const int j   = tid & (Hv - 1);   // hidden index owned by this thread
    const int hf  = tid >> 8;         // row-half 0/1
    const int r0  = hf * RT;
    const int b0  = blockIdx.x * Rv;  // batch tile base
    const int dir = blockIdx.y;       // 0 = fwd, 1 = bwd

    __shared__ __align__(16) float hs[Rv][Hv];   // h state, row-major
    __shared__ __align__(16) float xs[Rv][KIN];  // staged input rows

    const size_t g3 = (size_t)dir * 3 * Hv;
    const float* wir = wih + (g3 + j) * KIN;
    const float* wiz = wih + (g3 + Hv + j) * KIN;
    const float* win = wih + (g3 + 2 * Hv + j) * KIN;
    const float* whr = whh + (g3 + j) * Hv;
    const float* whz = whh + (g3 + Hv + j) * Hv;
    const float* whn = whh + (g3 + 2 * Hv + j) * Hv;
    const float bihr = bih[g3 + j],          bhhr = bhh[g3 + j];
    const float bihz = bih[g3 + Hv + j],     bhhz = bhh[g3 + Hv + j];
    const float bihn = bih[g3 + 2 * Hv + j], bhhn = bhh[g3 + 2 * Hv + j];

    float hold[RT];
    #pragma unroll
    for (int r = 0; r < RT; r++) { hold[r] = 0.0f; hs[r0 + r][j] = 0.0f; }
    __syncthreads();

    for (int s = 0; s < Tv; s++) {
        const int tt = dir ? (Tv - 1 - s) : s;

        // stage the Rv input rows for this step (coalesced float4)
        constexpr int NF4 = Rv * KIN / 4;
        for (int i = tid; i < NF4; i += NTH) {
            const int rr = i / (KIN / 4);
            const int cc = i % (KIN / 4);
            const float4* src;
            if (IS_L0)
                src = reinterpret_cast<const float4*>(
                          in + ((size_t)(b0 + rr) * Tv + tt) * Dv) + cc;
            else
                src = reinterpret_cast<const float4*>(
                          in + ((size_t)tt * Bv + (b0 + rr)) * (2 * Hv)) + cc;
            reinterpret_cast<float4*>(&xs[rr][0])[cc] = *src;
        }
        __syncthreads();

        ull ar[RT], az[RT], an[RT];
        #pragma unroll
        for (int r = 0; r < RT; r++) { ar[r] = 0ull; az[r] = 0ull; an[r] = 0ull; }

        // ---- gi = x . w_ih^T (fused) ----
        #pragma unroll 2
        for (int k = 0; k < KIN; k += 4) {
            const ulonglong2 w_r = *reinterpret_cast<const ulonglong2*>(wir + k);
            const ulonglong2 w_z = *reinterpret_cast<const ulonglong2*>(wiz + k);
            const ulonglong2 w_n = *reinterpret_cast<const ulonglong2*>(win + k);
            #pragma unroll
            for (int r = 0; r < RT; r++) {
                const ulonglong2 h2 =
                    *reinterpret_cast<const ulonglong2*>(&xs[r0 + r][k]);
                ffma2(ar[r], w_r.x, h2.x); ffma2(ar[r], w_r.y, h2.y);
                ffma2(az[r], w_z.x, h2.x); ffma2(az[r], w_z.y, h2.y);
                ffma2(an[r], w_n.x, h2.x); ffma2(an[r], w_n.y, h2.y);
            }
        }
        float gir[RT], giz[RT], gin[RT];
        #pragma unroll
        for (int r = 0; r < RT; r++) {
            gir[r] = hsum2(ar[r]); giz[r] = hsum2(az[r]); gin[r] = hsum2(an[r]);
            ar[r] = 0ull; az[r] = 0ull; an[r] = 0ull;
        }

        // ---- gh = h . w_hh^T ----
        #pragma unroll 2
        for (int k = 0; k < Hv; k += 4) {
            const ulonglong2 w_r = *reinterpret_cast<const ulonglong2*>(whr + k);
            const ulonglong2 w_z = *reinterpret_cast<const ulonglong2*>(whz + k);
            const ulonglong2 w_n = *reinterpret_cast<const ulonglong2*>(whn + k);
            #pragma unroll
            for (int r = 0; r < RT; r++) {
                const ulonglong2 h2 =
                    *reinterpret_cast<const ulonglong2*>(&hs[r0 + r][k]);
                ffma2(ar[r], w_r.x, h2.x); ffma2(ar[r], w_r.y, h2.y);
                ffma2(az[r], w_z.x, h2.x); ffma2(az[r], w_z.y, h2.y);
                ffma2(an[r], w_n.x, h2.x); ffma2(an[r], w_n.y, h2.y);
            }
        }

        // ---- gates + state update (PyTorch convention: b_hh_n inside r*) ----
        float hnew[RT];
        #pragma unroll
        for (int r = 0; r < RT; r++) {
            const float rr = sigm(gir[r] + bihr + hsum2(ar[r]) + bhhr);
            const float zz = sigm(giz[r] + bihz + hsum2(az[r]) + bhhz);
            const float nn = tanh_fast(gin[r] + bihn + rr * (hsum2(an[r]) + bhhn));
            hnew[r] = (1.0f - zz) * nn + zz * hold[r];
        }
        __syncthreads();  // all readers done with hs/xs of this step
        #pragma unroll
        for (int r = 0; r < RT; r++) {
            hold[r] = hnew[r];
            hs[r0 + r][j] = hnew[r];
            if (IS_L0)
                seq_out[((size_t)tt * Bv + (b0 + r0 + r)) * (2 * Hv) +
                        (size_t)dir * Hv + j] = hnew[r];
        }
    }

    if (!IS_L0) {
        // final hidden per direction: fwd -> out[:, :H], bwd -> out[:, H:]
        #pragma unroll
        for (int r = 0; r < RT; r++)
            fin_out[(size_t)(b0 + r0 + r) * (2 * Hv) + (size_t)dir * Hv + j] =
                hold[r];
    }
}

extern "C" void kernel_launch(void* const* d_in, const int* in_sizes, int n_in,
                              void* d_out, int out_size) {
    const float* x     = (const float*)d_in[0];
    const float* w_ih0 = (const float*)d_in[1];
    const float* w_hh0 = (const float*)d_in[2];
    const float* b_ih0 = (const float*)d_in[3];
    const float* b_hh0 = (const float*)d_in[4];
    const float* w_ih1 = (const float*)d_in[5];
    const float* w_hh1 = (const float*)d_in[6];
    const float* b_ih1 = (const float*)d_in[7];
    const float* b_hh1 = (const float*)d_in[8];
    float* out = (float*)d_out;

    float* h1 = nullptr;
    cudaGetSymbolAddress((void**)&h1, g_h1);  // host-side query, capture-safe

    dim3 grid(Bv / Rv, 2);
    gru_layer<Dv,     true ><<<grid, NTH>>>(x,  w_ih0, w_hh0, b_ih0, b_hh0, h1, nullptr);
    gru_layer<2 * Hv, false><<<grid, NTH>>>(h1, w_ih1, w_hh1, b_ih1, b_hh1, nullptr, out);
}

// round 10
// speedup vs baseline: 3.3166x; 3.3166x over previous
#include <cuda_runtime.h>

// 2-layer bidirectional GRU encoder, B=256, T=256, D=64, H=256.
// R7 redesign: coalesced k-split weight loads.
//   lane = (jo, ko): jo = lane>>3 selects one of 4 hidden outputs per warp
//   iteration; ko = lane&7 k-splits the dot product (8 lanes x 16B = 128B
//   contiguous per weight row -> 4 L1 wavefronts/LDG instead of 32).
//   Each weight fragment is reused across Rv=8 batch rows in registers.
//   Partials reduced over the 8 ko lanes via 3 bfly shuffles; lane ko owns
//   the gate update for batch row ko. FFMA2 throughout. Double-buffered h.

namespace {
constexpr int Bv  = 256;
constexpr int Tv  = 256;
constexpr int Dv  = 64;
constexpr int Hv  = 256;
constexpr int Rv  = 8;     // batch rows per CTA (== ko lanes)
constexpr int NTH = 512;   // 16 warps
constexpr int JW  = Hv / 16;  // 16 hidden outputs per warp
constexpr int PAD = 4;     // smem row pad (floats): keeps 16B align, kills conflicts
}

typedef unsigned long long ull;

// Layer-0 output sequence: [T][B][2H] fp32 = 128 MB scratch.
__device__ __align__(16) float g_h1[(size_t)Tv * Bv * 2 * Hv];

__device__ __forceinline__ void ffma2(ull &acc, ull a, ull b) {
    asm("fma.rn.f32x2 %0, %1, %2, %0;" : "+l"(acc) : "l"(a), "l"(b));
}
__device__ __forceinline__ float hsum2(ull v) {
    return __uint_as_float((unsigned)(v & 0xffffffffull)) +
           __uint_as_float((unsigned)(v >> 32));
}
__device__ __forceinline__ float sigm(float x) {
    return 1.0f / (1.0f + __expf(-x));
}
__device__ __forceinline__ float tanh_fast(float x) {
    float ax = fabsf(x);
    float e  = __expf(-2.0f * ax);
    float t  = (1.0f - e) / (1.0f + e);
    return copysignf(t, x);
}
// compile-time-unrolled dynamic pick from an 8-entry register array
__device__ __forceinline__ float sel8(const float v[8], int i) {
    float r = v[0];
    #pragma unroll
    for (int t = 1; t < 8; t++) r = (i == t) ? v[t] : r;
    return r;
}

template<int KIN, bool IS_L0>
__global__ void __launch_bounds__(NTH, 1)
gru_layer(const float* __restrict__ in,     // L0: x (B,T,D). L1: g_h1 (T,B,2H)
          const float* __restrict__ wih,    // (2, 3H, KIN)
          const float* __restrict__ whh,    // (2, 3H, H)
          const float* __restrict__ bih,    // (2, 3H)
          const float* __restrict__ bhh,    // (2, 3H)
          float* __restrict__ seq_out,      // L0: g_h1
          float* __restrict__ fin_out)      // L1: d_out (B, 2H)
{
    const int tid  = threadIdx.x;
    const int w    = tid >> 5;
    const int lane = tid & 31;
    const int ko   = lane & 7;    // k-split lane / owned batch row
    const int jo   = lane >> 3;   // hidden-output sub-lane (0..3)
    const int b0   = blockIdx.x * Rv;
    const int dir  = blockIdx.y;

    __shared__ __align__(16) float hs[2][Rv][Hv + PAD];  // double-buffered h
    __shared__ __align__(16) float xs[Rv][KIN + PAD];

    const size_t g3 = (size_t)dir * 3 * Hv;

    // zero h buffers
    for (int i = tid; i < 2 * Rv * (Hv + PAD); i += NTH)
        (&hs[0][0][0])[i] = 0.0f;
    __syncthreads();

    int p = 0;  // current h buffer
    for (int s = 0; s < Tv; s++) {
        const int tt = dir ? (Tv - 1 - s) : s;

        // ---- stage input rows for this step (coalesced float4) ----
        constexpr int NF4 = Rv * KIN / 4;
        for (int i = tid; i < NF4; i += NTH) {
            const int rr = i / (KIN / 4);
            const int cc = i % (KIN / 4);
            const float4* src;
            if (IS_L0)
                src = reinterpret_cast<const float4*>(
                          in + ((size_t)(b0 + rr) * Tv + tt) * Dv) + cc;
            else
                src = reinterpret_cast<const float4*>(
                          in + ((size_t)tt * Bv + (b0 + rr)) * (2 * Hv)) + cc;
            *reinterpret_cast<float4*>(&xs[rr][cc * 4]) = *src;
        }
        __syncthreads();

        const float (*hc)[Hv + PAD] = hs[p];      // read buffer
        float (*hn)[Hv + PAD]       = hs[p ^ 1];  // write buffer

        #pragma unroll 1
        for (int jj = 0; jj < 4; jj++) {
            const int j = w * JW + jj * 4 + jo;

            ull aR[Rv], aZ[Rv], aN[Rv];
            #pragma unroll
            for (int r = 0; r < Rv; r++) { aR[r] = 0; aZ[r] = 0; aN[r] = 0; }

            // ---- gi = x . w_ih^T (k-split over ko) ----
            {
                const float* wr_ = wih + (g3 + j) * KIN;
                const float* wz_ = wih + (g3 + Hv + j) * KIN;
                const float* wn_ = wih + (g3 + 2 * Hv + j) * KIN;
                #pragma unroll 2
                for (int k = 0; k < KIN; k += 32) {
                    const int kk = k + ko * 4;
                    const ulonglong2 w_r = *reinterpret_cast<const ulonglong2*>(wr_ + kk);
                    const ulonglong2 w_z = *reinterpret_cast<const ulonglong2*>(wz_ + kk);
                    const ulonglong2 w_n = *reinterpret_cast<const ulonglong2*>(wn_ + kk);
                    #pragma unroll
                    for (int r = 0; r < Rv; r++) {
                        const ulonglong2 h2 =
                            *reinterpret_cast<const ulonglong2*>(&xs[r][kk]);
                        ffma2(aR[r], w_r.x, h2.x); ffma2(aR[r], w_r.y, h2.y);
                        ffma2(aZ[r], w_z.x, h2.x); ffma2(aZ[r], w_z.y, h2.y);
                        ffma2(aN[r], w_n.x, h2.x); ffma2(aN[r], w_n.y, h2.y);
                    }
                }
            }
            // gi_n must stay separate from gh_n (PyTorch n-gate convention)
            float gin[Rv];
            #pragma unroll
            for (int r = 0; r < Rv; r++) { gin[r] = hsum2(aN[r]); aN[r] = 0; }

            // ---- gh = h . w_hh^T (r,z accumulate on top; n separate) ----
            {
                const float* ur_ = whh + (g3 + j) * Hv;
                const float* uz_ = whh + (g3 + Hv + j) * Hv;
                const float* un_ = whh + (g3 + 2 * Hv + j) * Hv;
                #pragma unroll 2
                for (int k = 0; k < Hv; k += 32) {
                    const int kk = k + ko * 4;
                    const ulonglong2 w_r = *reinterpret_cast<const ulonglong2*>(ur_ + kk);
                    const ulonglong2 w_z = *reinterpret_cast<const ulonglong2*>(uz_ + kk);
                    const ulonglong2 w_n = *reinterpret_cast<const ulonglong2*>(un_ + kk);
                    #pragma unroll
                    for (int r = 0; r < Rv; r++) {
                        const ulonglong2 h2 =
                            *reinterpret_cast<const ulonglong2*>(&hc[r][kk]);
                        ffma2(aR[r], w_r.x, h2.x); ffma2(aR[r], w_r.y, h2.y);
                        ffma2(aZ[r], w_z.x, h2.x); ffma2(aZ[r], w_z.y, h2.y);
                        ffma2(aN[r], w_n.x, h2.x); ffma2(aN[r], w_n.y, h2.y);
                    }
                }
            }

            float vR[Rv], vZ[Rv], vN[Rv];
            #pragma unroll
            for (int r = 0; r < Rv; r++) {
                vR[r] = hsum2(aR[r]); vZ[r] = hsum2(aZ[r]); vN[r] = hsum2(aN[r]);
            }
            // ---- reduce partials over the 8 ko lanes (bfly, stays in-group) ----
            #pragma unroll
            for (int st = 1; st < 8; st <<= 1) {
                #pragma unroll
                for (int r = 0; r < Rv; r++) {
                    vR[r]  += __shfl_xor_sync(0xffffffffu, vR[r],  st);
                    vZ[r]  += __shfl_xor_sync(0xffffffffu, vZ[r],  st);
                    vN[r]  += __shfl_xor_sync(0xffffffffu, vN[r],  st);
                    gin[r] += __shfl_xor_sync(0xffffffffu, gin[r], st);
                }
            }

            // ---- gate update: lane handles (row = ko, hidden = j) ----
            const float bR  = bih[g3 + j]          + bhh[g3 + j];
            const float bZ  = bih[g3 + Hv + j]     + bhh[g3 + Hv + j];
            const float bIN = bih[g3 + 2 * Hv + j];
            const float bHN = bhh[g3 + 2 * Hv + j];

            const float rg = sigm(sel8(vR, ko) + bR);
            const float zg = sigm(sel8(vZ, ko) + bZ);
            const float ng = tanh_fast(sel8(gin, ko) + bIN +
                                       rg * (sel8(vN, ko) + bHN));
            const float hv = (1.0f - zg) * ng + zg * hc[ko][j];

            hn[ko][j] = hv;  // write into next-step buffer (no race)
            if (IS_L0)
                seq_out[((size_t)tt * Bv + (b0 + ko)) * (2 * Hv) +
                        (size_t)dir * Hv + j] = hv;
        }
        __syncthreads();  // hn complete + xs reads done before next stage
        p ^= 1;
    }

    if (!IS_L0) {
        // final hidden per direction: fwd -> out[:, :H], bwd -> out[:, H:]
        #pragma unroll 1
        for (int jj = 0; jj < 4; jj++) {
            const int j = w * JW + jj * 4 + jo;
            fin_out[(size_t)(b0 + ko) * (2 * Hv) + (size_t)dir * Hv + j] =
                hs[p][ko][j];
        }
    }
}

extern "C" void kernel_launch(void* const* d_in, const int* in_sizes, int n_in,
                              void* d_out, int out_size) {
    const float* x     = (const float*)d_in[0];
    const float* w_ih0 = (const float*)d_in[1];
    const float* w_hh0 = (const float*)d_in[2];
    const float* b_ih0 = (const float*)d_in[3];
    const float* b_hh0 = (const float*)d_in[4];
    const float* w_ih1 = (const float*)d_in[5];
    const float* w_hh1 = (const float*)d_in[6];
    const float* b_ih1 = (const float*)d_in[7];
    const float* b_hh1 = (const float*)d_in[8];
    float* out = (float*)d_out;

    float* h1 = nullptr;
    cudaGetSymbolAddress((void**)&h1, g_h1);  // host-side query, capture-safe

    dim3 grid(Bv / Rv, 2);
    gru_layer<Dv,     true ><<<grid, NTH>>>(x,  w_ih0, w_hh0, b_ih0, b_hh0, h1, nullptr);
    gru_layer<2 * Hv, false><<<grid, NTH>>>(h1, w_ih1, w_hh1, b_ih1, b_hh1, nullptr, out);
}

// round 11
// speedup vs baseline: 6.6020x; 1.9906x over previous
#include <cuda_runtime.h>

// 2-layer bidirectional GRU encoder, B=256, T=256, D=64, H=256.
// R11: 2-CTA cluster splits the gate (j) dimension.
//   Cluster = (batch-tile, dir); rank c owns j in [c*128, c*128+128).
//   Each CTA holds a FULL copy of h (needed for the gh dot products); after
//   computing its half of h_new it stores those values into the peer's
//   next-step h buffer via mapa + st.shared::cluster, then barrier.cluster.
//   -> 128 CTAs (fills the chip), per-CTA weight traffic & FFMA halved.
// Also: merging-butterfly reduction (7 shfl/gate, lane ko ends owning row
// ko — no sel8) and biases preloaded into registers.

namespace {
constexpr int Bv  = 256;
constexpr int Tv  = 256;
constexpr int Dv  = 64;
constexpr int Hv  = 256;
constexpr int Rv  = 8;      // batch rows per cluster (== ko lanes)
constexpr int NTH = 512;    // 16 warps
constexpr int JH  = Hv / 2; // j-range per CTA (128)
constexpr int NJJ = 2;      // jj iterations (each warp: 8 j = 2 * 4 jo)
constexpr int PAD = 4;      // smem row pad (floats)
}

typedef unsigned long long ull;

// Layer-0 output sequence: [T][B][2H] fp32 = 128 MB scratch.
__device__ __align__(16) float g_h1[(size_t)Tv * Bv * 2 * Hv];

__device__ __forceinline__ void ffma2(ull &acc, ull a, ull b) {
    asm("fma.rn.f32x2 %0, %1, %2, %0;" : "+l"(acc) : "l"(a), "l"(b));
}
__device__ __forceinline__ float hsum2(ull v) {
    return __uint_as_float((unsigned)(v & 0xffffffffull)) +
           __uint_as_float((unsigned)(v >> 32));
}
__device__ __forceinline__ float sigm(float x) {
    return 1.0f / (1.0f + __expf(-x));
}
__device__ __forceinline__ float tanh_fast(float x) {
    float ax = fabsf(x);
    float e  = __expf(-2.0f * ax);
    float t  = (1.0f - e) / (1.0f + e);
    return copysignf(t, x);
}
__device__ __forceinline__ unsigned ctarank() {
    unsigned r; asm("mov.u32 %0, %%cluster_ctarank;" : "=r"(r)); return r;
}
__device__ __forceinline__ unsigned mapa_peer(unsigned local_addr, unsigned rank) {
    unsigned r;
    asm("mapa.shared::cluster.u32 %0, %1, %2;" : "=r"(r) : "r"(local_addr), "r"(rank));
    return r;
}
__device__ __forceinline__ void st_cluster_f32(unsigned addr, float v) {
    asm volatile("st.shared::cluster.f32 [%0], %1;" :: "r"(addr), "f"(v) : "memory");
}
#define CLUSTER_SYNC_() do {                                          \
    asm volatile("barrier.cluster.arrive.aligned;" ::: "memory");     \
    asm volatile("barrier.cluster.wait.aligned;"   ::: "memory");     \
} while (0)

// Reduce 8 register arrays over the 8 ko-lanes; lane ko returns sum of v[ko].
// Merging butterfly: 7 shuffles, depth 3.
__device__ __forceinline__ float tree8(const float v[8], int ko) {
    float u[4];
    #pragma unroll
    for (int i = 0; i < 4; i++) {
        const float a = v[2 * i], b = v[2 * i + 1];
        const float send = (ko & 1) ? a : b;
        const float recv = __shfl_xor_sync(0xffffffffu, send, 1);
        u[i] = ((ko & 1) ? b : a) + recv;
    }
    float w2[2];
    #pragma unroll
    for (int i = 0; i < 2; i++) {
        const float a = u[2 * i], b = u[2 * i + 1];
        const float send = (ko & 2) ? a : b;
        const float recv = __shfl_xor_sync(0xffffffffu, send, 2);
        w2[i] = ((ko & 2) ? b : a) + recv;
    }
    const float a = w2[0], b = w2[1];
    const float send = (ko & 4) ? a : b;
    const float recv = __shfl_xor_sync(0xffffffffu, send, 4);
    return ((ko & 4) ? b : a) + recv;
}

template<int KIN, bool IS_L0>
__global__ void __launch_bounds__(NTH, 1) __cluster_dims__(2, 1, 1)
gru_layer(const float* __restrict__ in,     // L0: x (B,T,D). L1: g_h1 (T,B,2H)
          const float* __restrict__ wih,    // (2, 3H, KIN)
          const float* __restrict__ whh,    // (2, 3H, H)
          const float* __restrict__ bih,    // (2, 3H)
          const float* __restrict__ bhh,    // (2, 3H)
          float* __restrict__ seq_out,      // L0: g_h1
          float* __restrict__ fin_out)      // L1: d_out (B, 2H)
{
    const int tid  = threadIdx.x;
    const int w    = tid >> 5;
    const int lane = tid & 31;
    const int ko   = lane & 7;    // k-split lane / owned batch row
    const int jo   = lane >> 3;   // hidden-output sub-lane (0..3)
    const unsigned c = ctarank(); // cluster rank: j-half
    const int b0   = (blockIdx.x >> 1) * Rv;
    const int dir  = blockIdx.y;

    __shared__ __align__(16) float hs[2][Rv][Hv + PAD];  // full h, dbl-buffered
    __shared__ __align__(16) float xs[Rv][KIN + PAD];

    const size_t g3   = (size_t)dir * 3 * Hv;
    const int jbase = (int)c * JH + w * (JH / 16) + jo;  // + jj*4

    // peer base address of hs (for cross-CTA h_new writes)
    const unsigned my_hs   = (unsigned)__cvta_generic_to_shared(&hs[0][0][0]);
    const unsigned peer_hs = mapa_peer(my_hs, c ^ 1u);

    // preload biases for this thread's NJJ j-values
    float bR_[NJJ], bZ_[NJJ], bIN_[NJJ], bHN_[NJJ];
    #pragma unroll
    for (int jj = 0; jj < NJJ; jj++) {
        const int j = jbase + jj * 4;
        bR_[jj]  = bih[g3 + j]          + bhh[g3 + j];
        bZ_[jj]  = bih[g3 + Hv + j]     + bhh[g3 + Hv + j];
        bIN_[jj] = bih[g3 + 2 * Hv + j];
        bHN_[jj] = bhh[g3 + 2 * Hv + j];
    }

    // zero both h buffers (each CTA zeroes its own full copy)
    for (int i = tid; i < 2 * Rv * (Hv + PAD); i += NTH)
        (&hs[0][0][0])[i] = 0.0f;
    __syncthreads();
    CLUSTER_SYNC_();

    int p = 0;
    for (int s = 0; s < Tv; s++) {
        const int tt = dir ? (Tv - 1 - s) : s;

        // ---- stage input rows for this step (coalesced float4) ----
        constexpr int NF4 = Rv * KIN / 4;
        for (int i = tid; i < NF4; i += NTH) {
            const int rr = i / (KIN / 4);
            const int cc = i % (KIN / 4);
            const float4* src;
            if (IS_L0)
                src = reinterpret_cast<const float4*>(
                          in + ((size_t)(b0 + rr) * Tv + tt) * Dv) + cc;
            else
                src = reinterpret_cast<const float4*>(
                          in + ((size_t)tt * Bv + (b0 + rr)) * (2 * Hv)) + cc;
            *reinterpret_cast<float4*>(&xs[rr][cc * 4]) = *src;
        }
        __syncthreads();

        const float (*hc)[Hv + PAD] = hs[p];
        float (*hn)[Hv + PAD]       = hs[p ^ 1];
        const unsigned peer_hn =
            peer_hs + (unsigned)((p ^ 1) * Rv * (Hv + PAD)) * 4u;

        #pragma unroll 1
        for (int jj = 0; jj < NJJ; jj++) {
            const int j = jbase + jj * 4;

            ull aR[Rv], aZ[Rv], aN[Rv];
            #pragma unroll
            for (int r = 0; r < Rv; r++) { aR[r] = 0; aZ[r] = 0; aN[r] = 0; }

            // ---- gi = x . w_ih^T (k-split over ko) ----
            {
                const float* wr_ = wih + (g3 + j) * KIN;
                const float* wz_ = wih + (g3 + Hv + j) * KIN;
                const float* wn_ = wih + (g3 + 2 * Hv + j) * KIN;
                #pragma unroll 2
                for (int k = 0; k < KIN; k += 32) {
                    const int kk = k + ko * 4;
                    const ulonglong2 w_r = *reinterpret_cast<const ulonglong2*>(wr_ + kk);
                    const ulonglong2 w_z = *reinterpret_cast<const ulonglong2*>(wz_ + kk);
                    const ulonglong2 w_n = *reinterpret_cast<const ulonglong2*>(wn_ + kk);
                    #pragma unroll
                    for (int r = 0; r < Rv; r++) {
                        const ulonglong2 h2 =
                            *reinterpret_cast<const ulonglong2*>(&xs[r][kk]);
                        ffma2(aR[r], w_r.x, h2.x); ffma2(aR[r], w_r.y, h2.y);
                        ffma2(aZ[r], w_z.x, h2.x); ffma2(aZ[r], w_z.y, h2.y);
                        ffma2(aN[r], w_n.x, h2.x); ffma2(aN[r], w_n.y, h2.y);
                    }
                }
            }
            // gi_n must stay separate from gh_n (PyTorch n-gate convention)
            float gin[Rv];
            #pragma unroll
            for (int r = 0; r < Rv; r++) { gin[r] = hsum2(aN[r]); aN[r] = 0; }

            // ---- gh = h . w_hh^T (r,z accumulate on top; n separate) ----
            {
                const float* ur_ = whh + (g3 + j) * Hv;
                const float* uz_ = whh + (g3 + Hv + j) * Hv;
                const float* un_ = whh + (g3 + 2 * Hv + j) * Hv;
                #pragma unroll 2
                for (int k = 0; k < Hv; k += 32) {
                    const int kk = k + ko * 4;
                    const ulonglong2 w_r = *reinterpret_cast<const ulonglong2*>(ur_ + kk);
                    const ulonglong2 w_z = *reinterpret_cast<const ulonglong2*>(uz_ + kk);
                    const ulonglong2 w_n = *reinterpret_cast<const ulonglong2*>(un_ + kk);
                    #pragma unroll
                    for (int r = 0; r < Rv; r++) {
                        const ulonglong2 h2 =
                            *reinterpret_cast<const ulonglong2*>(&hc[r][kk]);
                        ffma2(aR[r], w_r.x, h2.x); ffma2(aR[r], w_r.y, h2.y);
                        ffma2(aZ[r], w_z.x, h2.x); ffma2(aZ[r], w_z.y, h2.y);
                        ffma2(aN[r], w_n.x, h2.x); ffma2(aN[r], w_n.y, h2.y);
                    }
                }
            }

            float vR[Rv], vZ[Rv], vN[Rv];
            #pragma unroll
            for (int r = 0; r < Rv; r++) {
                vR[r] = hsum2(aR[r]); vZ[r] = hsum2(aZ[r]); vN[r] = hsum2(aN[r]);
            }
            // ---- merging butterfly: lane ko ends owning row ko ----
            const float sR = tree8(vR,  ko);
            const float sZ = tree8(vZ,  ko);
            const float sN = tree8(vN,  ko);
            const float sI = tree8(gin, ko);

            // ---- gate update: lane handles (row = ko, hidden = j) ----
            const float rg = sigm(sR + bR_[jj]);
            const float zg = sigm(sZ + bZ_[jj]);
            const float ng = tanh_fast(sI + bIN_[jj] + rg * (sN + bHN_[jj]));
            const float hv = (1.0f - zg) * ng + zg * hc[ko][j];

            hn[ko][j] = hv;                               // local copy
            st_cluster_f32(peer_hn + (unsigned)(ko * (Hv + PAD) + j) * 4u, hv);
            if (IS_L0)
                seq_out[((size_t)tt * Bv + (b0 + ko)) * (2 * Hv) +
                        (size_t)dir * Hv + j] = hv;
        }
        // cluster barrier: peer's h_new writes visible; also acts as CTA sync
        CLUSTER_SYNC_();
        p ^= 1;
    }

    if (!IS_L0) {
        // final hidden per direction: fwd -> out[:, :H], bwd -> out[:, H:]
        #pragma unroll
        for (int jj = 0; jj < NJJ; jj++) {
            const int j = jbase + jj * 4;
            fin_out[(size_t)(b0 + ko) * (2 * Hv) + (size_t)dir * Hv + j] =
                hs[p][ko][j];
        }
    }
}

extern "C" void kernel_launch(void* const* d_in, const int* in_sizes, int n_in,
                              void* d_out, int out_size) {
    const float* x     = (const float*)d_in[0];
    const float* w_ih0 = (const float*)d_in[1];
    const float* w_hh0 = (const float*)d_in[2];
    const float* b_ih0 = (const float*)d_in[3];
    const float* b_hh0 = (const float*)d_in[4];
    const float* w_ih1 = (const float*)d_in[5];
    const float* w_hh1 = (const float*)d_in[6];
    const float* b_ih1 = (const float*)d_in[7];
    const float* b_hh1 = (const float*)d_in[8];
    float* out = (float*)d_out;

    float* h1 = nullptr;
    cudaGetSymbolAddress((void**)&h1, g_h1);  // host-side query, capture-safe

    dim3 grid(2 * (Bv / Rv), 2);  // (tile, rank) x dir = 128 CTAs
    gru_layer<Dv,     true ><<<grid, NTH>>>(x,  w_ih0, w_hh0, b_ih0, b_hh0, h1, nullptr);
    gru_layer<2 * Hv, false><<<grid, NTH>>>(h1, w_ih1, w_hh1, b_ih1, b_hh1, nullptr, out);
}